// round 7
// baseline (speedup 1.0000x reference)
#include <cuda_runtime.h>
#include <cuda_bf16.h>

// LIF scan — register double-buffered LDG pipeline, no smem, no syncs.
//   out[b,0,h] = 0
//   for k=1..T-1: reset=(V>1); V = 0.9V + z[b,k-1,h] - reset; out[b,k,h] = (V>1)
//
// 1 thread <-> 1 (b,h) chain; 128 blocks x 128 threads.
// Loads issued in phase-separated batches of 32 (two live batches = two wait
// groups <= 6 SB slots, unlike the 64-deep interleaved ring that aliased).
// Issue-to-consume distance ~1 full compute phase (~600cyc) hides DRAM.
// Step body identical to the rel_err=0.0 version: t=z-sf; V=fma(.9,V,t); sf=V>1.

#define Bb    32
#define T     1024
#define Hh    512
#define BATCH 32   // steps per batch; 31 full batches + 31-step tail = 1023

__global__ __launch_bounds__(128, 1)
void lif_kernel(const float* __restrict__ z, float* __restrict__ out) {
    const int tid = blockIdx.x * blockDim.x + threadIdx.x;  // 0..16383
    const int b = tid >> 9;
    const int h = tid & 511;

    const float* zp = z   + (size_t)b * T * Hh + h;
    float*       op = out + (size_t)b * T * Hh + h;

    op[0] = 0.0f;                      // k=0 row (d_out poisoned)

    float A[BATCH], B[BATCH];

    // prologue: batch 0 (input rows 0..31)
    #pragma unroll
    for (int r = 0; r < BATCH; ++r) A[r] = zp[r * Hh];

    const float* zl = zp + BATCH * Hh;  // next load base (row 32)
    float*       os = op + Hh;          // store base: input row j -> out row j+1

    float V  = 0.0f;
    float sf = 0.0f;                    // spike == next step's reset

    // 15 double-iterations: compute batches 0..29, prefetch 1..30
    #pragma unroll 1
    for (int it = 0; it < 15; ++it) {
        // issue batch (2it+1) -> B
        #pragma unroll
        for (int r = 0; r < BATCH; ++r) B[r] = zl[r * Hh];
        zl += BATCH * Hh;

        // consume batch (2it) from A
        #pragma unroll
        for (int r = 0; r < BATCH; ++r) {
            float t = A[r] - sf;
            V = fmaf(0.9f, V, t);
            sf = (V > 1.0f) ? 1.0f : 0.0f;
            os[r * Hh] = sf;
        }
        os += BATCH * Hh;

        // issue batch (2it+2) -> A
        #pragma unroll
        for (int r = 0; r < BATCH; ++r) A[r] = zl[r * Hh];
        zl += BATCH * Hh;

        // consume batch (2it+1) from B
        #pragma unroll
        for (int r = 0; r < BATCH; ++r) {
            float t = B[r] - sf;
            V = fmaf(0.9f, V, t);
            sf = (V > 1.0f) ? 1.0f : 0.0f;
            os[r * Hh] = sf;
        }
        os += BATCH * Hh;
    }

    // epilogue: A holds batch 30 (rows 960..991); zl at row 992.
    // prefetch tail rows 992..1023 (row 1023 exists; only 31 consumed)
    #pragma unroll
    for (int r = 0; r < BATCH; ++r) B[r] = zl[r * Hh];

    #pragma unroll
    for (int r = 0; r < BATCH; ++r) {          // steps 960..991
        float t = A[r] - sf;
        V = fmaf(0.9f, V, t);
        sf = (V > 1.0f) ? 1.0f : 0.0f;
        os[r * Hh] = sf;
    }
    os += BATCH * Hh;

    #pragma unroll
    for (int r = 0; r < BATCH - 1; ++r) {      // steps 992..1022
        float t = B[r] - sf;
        V = fmaf(0.9f, V, t);
        sf = (V > 1.0f) ? 1.0f : 0.0f;
        os[r * Hh] = sf;
    }
}

extern "C" void kernel_launch(void* const* d_in, const int* in_sizes, int n_in,
                              void* d_out, int out_size) {
    const float* z = (const float*)d_in[0];
    float* out = (float*)d_out;
    lif_kernel<<<(Bb * Hh) / 128, 128>>>(z, out);
}

// round 8
// speedup vs baseline: 1.4628x; 1.4628x over previous
#include <cuda_runtime.h>
#include <cuda_pipeline.h>

// LIF scan — warp-local cp.async pipeline (16B granules), syncwarp-only.
//   out[b,0,h] = 0
//   for k=1..T-1: reset=(V>1); V = 0.9V + z[b,k-1,h] - reset; out[b,k,h] = (V>1)
//
// 1 thread <-> 1 (b,h) chain; 128 blocks x 128 threads (1 CTA/SM).
// Each warp owns 32 contiguous h-columns; its threads cooperatively cp.async
// 16B granules (4 columns each) -> 4x fewer LDGSTS than the 4B/thread version.
// Visibility is warp-internal only => __syncwarp per stage, no __syncthreads.
// Critical path per step is FSETP->FSEL->FFMA (12 cyc): zm1 precomputed
// off-chain, select z vs z-1, fma. Same grouping as the rel_err=0 versions.

#define Bb    32
#define T     1024
#define Hh    512

#define HT      128            // h per block (= threads)
#define SROWS   16             // t-steps per stage
#define NSTAGE  8              // pipeline depth (64 KB smem)
#define NST     (T / SROWS)    // 64 stages; last stage: 15 valid steps

__global__ __launch_bounds__(HT, 1)
void lif_kernel(const float* __restrict__ z, float* __restrict__ out) {
    __shared__ float sbuf[NSTAGE][SROWS][HT];   // 64 KB

    const int tid  = threadIdx.x;
    const int lane = tid & 31;
    const int wrp  = tid >> 5;
    const int b    = blockIdx.x >> 2;
    const int h0   = (blockIdx.x & 3) * HT;

    // consumer column
    const float* zcol = z   + (size_t)b * T * Hh + h0 + tid;
    float*       op   = out + (size_t)b * T * Hh + h0 + tid;

    // loader granule: warp covers columns [32*wrp, 32*wrp+32); this thread
    // loads 16B (4 cols) at column gcol for rows rbase, rbase+4, rbase+8, +12.
    const int gcol  = wrp * 32 + (lane & 7) * 4;
    const int rbase = lane >> 3;                // 0..3
    const float* zg = z + (size_t)b * T * Hh + h0 + gcol;

    // k = 0 output is zero (d_out poisoned).
    op[0] = 0.0f;

    // ── prologue: fill stages 0..NSTAGE-2 ────────────────────────────────
    #pragma unroll
    for (int s = 0; s < NSTAGE - 1; ++s) {
        #pragma unroll
        for (int k = 0; k < 4; ++k) {
            const int r = rbase + k * 4;
            __pipeline_memcpy_async(&sbuf[s][r][gcol],
                                    zg + (size_t)(s * SROWS + r) * Hh, 16);
        }
        __pipeline_commit();
    }

    float V = 0.0f;
    bool  p = false;    // reset predicate == previous spike

    for (int st = 0; st < NST; ++st) {
        __pipeline_wait_prior(NSTAGE - 2);   // my granules of stage st done
        __syncwarp();                        // make them visible warp-wide

        // refill stage st+NSTAGE-1 into the slot freed at stage st-1
        const int sn = st + NSTAGE - 1;
        if (sn < NST) {
            const int slot = sn & (NSTAGE - 1);
            #pragma unroll
            for (int k = 0; k < 4; ++k) {
                const int r = rbase + k * 4;
                __pipeline_memcpy_async(&sbuf[slot][r][gcol],
                                        zg + (size_t)(sn * SROWS + r) * Hh, 16);
            }
        }
        __pipeline_commit();                 // uniform group count

        const float* sp  = &sbuf[st & (NSTAGE - 1)][0][tid];
        float*       opk = op + (size_t)(st * SROWS + 1) * Hh;

        if (st < NST - 1) {
            #pragma unroll
            for (int r = 0; r < SROWS; ++r) {
                float zin = sp[r * HT];
                float zm1 = zin - 1.0f;           // off critical path
                float inj = p ? zm1 : zin;        // FSEL (chain)
                V = fmaf(0.9f, V, inj);           // FFMA (chain)
                p = V > 1.0f;                     // FSETP (chain)
                opk[r * Hh] = p ? 1.0f : 0.0f;    // off-chain FSEL + STG
            }
        } else {
            #pragma unroll
            for (int r = 0; r < SROWS - 1; ++r) { // steps 1008..1022
                float zin = sp[r * HT];
                float zm1 = zin - 1.0f;
                float inj = p ? zm1 : zin;
                V = fmaf(0.9f, V, inj);
                p = V > 1.0f;
                opk[r * Hh] = p ? 1.0f : 0.0f;
            }
        }
    }
}

extern "C" void kernel_launch(void* const* d_in, const int* in_sizes, int n_in,
                              void* d_out, int out_size) {
    const float* z = (const float*)d_in[0];
    float* out = (float*)d_out;
    lif_kernel<<<(Bb * Hh) / HT, HT>>>(z, out);
}